// round 16
// baseline (speedup 1.0000x reference)
#include <cuda_runtime.h>
#include <cuda_fp16.h>
#include <cstdint>

// Problem constants (fixed by dataset)
#define N_NODES 50000
#define N_EDGES 800000
#define F_IN   128
#define F_H1   256
#define F_H    128
#define F_OUT  32
#define M_PAD  50048   // 391 * 128

// ---------------- scratch (static device globals) ---------------------------
__device__ int   g_count [N_NODES];
__device__ float g_dinv  [M_PAD];        // pad rows stay 0
__device__ int   g_rowptr[N_NODES + 1];
__device__ int   g_cursor[N_NODES];
__device__ int   g_col   [N_EDGES];      // stores src<<8 (byte offset, 256B rows)
__device__ int   g_pfx   [64];           // chained-scan prefix (+1; 0 = not ready)

// fp16 activations
__device__ __half g_x16[(size_t)N_NODES * F_IN];   // dinv-prescaled fp16 x
__device__ __half g_a1 [(size_t)M_PAD * F_IN];     // agg1 out; pad rows stay 0
__device__ __half g_g2 [(size_t)M_PAD * F_H];      // dinv*(relu(a1@W1+b1)@W2)
__device__ __half g_g3 [(size_t)M_PAD * F_OUT];
// transposed fp16 weights [N][K] (K-major rows)
__device__ __half g_w1[256 * 128];
__device__ __half g_w2[128 * 256];
__device__ __half g_w3[32 * 128];

// ---------------- PTX helpers ------------------------------------------------
__device__ __forceinline__ uint32_t smem_u32(const void* p) {
    uint32_t a;
    asm("{ .reg .u64 t; cvta.to.shared.u64 t, %1; cvt.u32.u64 %0, t; }"
        : "=r"(a) : "l"(p));
    return a;
}
__device__ __forceinline__ void ldsm4(uint32_t addr, uint32_t r[4]) {
    asm volatile("ldmatrix.sync.aligned.m8n8.x4.shared.b16 {%0,%1,%2,%3}, [%4];"
                 : "=r"(r[0]), "=r"(r[1]), "=r"(r[2]), "=r"(r[3]) : "r"(addr));
}
__device__ __forceinline__ void ldsm2(uint32_t addr, uint32_t r[2]) {
    asm volatile("ldmatrix.sync.aligned.m8n8.x2.shared.b16 {%0,%1}, [%2];"
                 : "=r"(r[0]), "=r"(r[1]) : "r"(addr));
}
__device__ __forceinline__ void mma16816h(float* c, const uint32_t* a, const uint32_t* b) {
    asm volatile(
        "mma.sync.aligned.m16n8k16.row.col.f32.f16.f16.f32 "
        "{%0,%1,%2,%3}, {%4,%5,%6,%7}, {%8,%9}, {%0,%1,%2,%3};"
        : "+f"(c[0]), "+f"(c[1]), "+f"(c[2]), "+f"(c[3])
        : "r"(a[0]), "r"(a[1]), "r"(a[2]), "r"(a[3]), "r"(b[0]), "r"(b[1]));
}
__device__ __forceinline__ void cp16(uint32_t saddr, const void* gaddr) {
    asm volatile("cp.async.cg.shared.global [%0], [%1], 16;"
                 :: "r"(saddr), "l"(gaddr));
}
#define CP_COMMIT() asm volatile("cp.async.commit_group;" ::: "memory")

// ---------------- launch 1: fused prep (degree(x4) + W transpose + flags) ----
__global__ __launch_bounds__(256)
void prep_kernel(const int* __restrict__ ei,
                 const float* __restrict__ W1, const float* __restrict__ W2,
                 const float* __restrict__ W3,
                 __half* w1, __half* w2, __half* w3,
                 int e, int B_deg, int B_w) {
    int bid = blockIdx.x, tid = threadIdx.x;
    if (bid < B_deg) {
        int i0 = (bid * 256 + tid) * 4;
        if (i0 + 4 <= e) {
            int4 d = *reinterpret_cast<const int4*>(ei + e + i0);
            atomicAdd(&g_count[d.x], 1);
            atomicAdd(&g_count[d.y], 1);
            atomicAdd(&g_count[d.z], 1);
            atomicAdd(&g_count[d.w], 1);
        } else {
            for (int j = i0; j < e; j++) atomicAdd(&g_count[ei[e + j]], 1);
        }
    } else if (bid < B_deg + B_w) {
        int idx = (bid - B_deg) * 256 + tid;
        if (idx < 32768) {                               // W1 [128,256] -> [256][128]
            int nn = idx / 128, k = idx % 128;
            w1[idx] = __float2half(W1[k * 256 + nn]);
        } else if (idx < 65536) {                        // W2 [256,128] -> [128][256]
            int i2 = idx - 32768;
            int nn = i2 / 256, k = i2 % 256;
            w2[i2] = __float2half(W2[k * 128 + nn]);
        } else if (idx < 65536 + 4096) {                 // W3 [128,32] -> [32][128]
            int i3 = idx - 65536;
            int nn = i3 / 128, k = i3 % 128;
            w3[i3] = __float2half(W3[k * 32 + nn]);
        }
    } else {
        if (tid < 64) g_pfx[tid] = 0;
    }
}

// ---------------- launch 2: chained single-pass scan -------------------------
__global__ __launch_bounds__(1024)
void scan_chained_kernel(int n, int nb) {
    __shared__ int temp[1024];
    __shared__ int pfx_sh;
    int bid = blockIdx.x, tid = threadIdx.x;
    int i = bid * 1024 + tid;
    int v = (i < n) ? g_count[i] : 0;
    if (i < n) {
        g_dinv[i]  = rsqrtf((float)(v + 1));
        g_count[i] = 0;
    }
    temp[tid] = v;
    __syncthreads();
    #pragma unroll
    for (int off = 1; off < 1024; off <<= 1) {
        int t = (tid >= off) ? temp[tid - off] : 0;
        __syncthreads();
        temp[tid] += t;
        __syncthreads();
    }
    if (tid == 0) {
        int p = 0;
        if (bid > 0) {
            while ((p = atomicAdd(&g_pfx[bid - 1], 0)) == 0) __nanosleep(20);
            p -= 1;
        }
        atomicExch(&g_pfx[bid], p + temp[1023] + 1);
        pfx_sh = p;
    }
    __syncthreads();
    int base = pfx_sh;
    if (i < n) {
        int excl = base + temp[tid] - v;
        g_rowptr[i] = excl;
        g_cursor[i] = excl;
    }
    if (bid == nb - 1 && tid == 1023) g_rowptr[n] = base + temp[1023];
}

// ---------------- launch 3: FUSED csr-fill + x-convert -----------------------
__global__ __launch_bounds__(256)
void convfill_kernel(const float* __restrict__ x, __half* __restrict__ x16,
                     const int* __restrict__ ei, int n, int e, int B_fill) {
    int bid = blockIdx.x, tid = threadIdx.x;
    if (bid < B_fill) {
        int i = bid * 256 + tid;
        if (i < e) {
            int src = ei[i];
            int dst = ei[e + i];
            int pos = atomicAdd(&g_cursor[dst], 1);
            g_col[pos] = src << 8;
        }
    } else {
        int i = (bid - B_fill) * 256 + tid;
        int node = i >> 4, lane = i & 15;
        if (node >= n) return;
        float di = g_dinv[node];
        const float4* xv = (const float4*)x;
        float4 a = xv[(size_t)node * 32 + lane * 2];
        float4 b = xv[(size_t)node * 32 + lane * 2 + 1];
        __half2 h0 = __floats2half2_rn(di * a.x, di * a.y);
        __half2 h1 = __floats2half2_rn(di * a.z, di * a.w);
        __half2 h2 = __floats2half2_rn(di * b.x, di * b.y);
        __half2 h3 = __floats2half2_rn(di * b.z, di * b.w);
        uint4 o;
        o.x = *reinterpret_cast<uint32_t*>(&h0);
        o.y = *reinterpret_cast<uint32_t*>(&h1);
        o.z = *reinterpret_cast<uint32_t*>(&h2);
        o.w = *reinterpret_cast<uint32_t*>(&h3);
        *reinterpret_cast<uint4*>(x16 + (size_t)node * F_IN + lane * 8) = o;
    }
}

// ---------------- agg primitives (NO shfl — proven per-thread loads) ---------
__device__ __forceinline__ void add8(float* acc, uint4 v) {
    const __half2* h = reinterpret_cast<const __half2*>(&v);
    #pragma unroll
    for (int q = 0; q < 4; q++) {
        float2 f = __half22float2(h[q]);
        acc[2 * q] += f.x; acc[2 * q + 1] += f.y;
    }
}
__device__ __forceinline__ uint4 hadd2x4(uint4 a, uint4 b) {
    const __half2* pa = reinterpret_cast<const __half2*>(&a);
    const __half2* pb = reinterpret_cast<const __half2*>(&b);
    uint4 r;
    __half2* pr = reinterpret_cast<__half2*>(&r);
    #pragma unroll
    for (int q = 0; q < 4; q++) pr[q] = __hadd2(pa[q], pb[q]);
    return r;
}

// agg body: node's self row + edge sum, 8-feat lane, depth-3 fp16 tree.
// g rows 256B (SH=0) or scaled via SH. Per-thread g_col loads (round-14 proven).
template <int SH>
__device__ __forceinline__ void agg_node(const char* base, uint32_t self_off,
                                         int node, float* acc) {
    add8(acc, *reinterpret_cast<const uint4*>(base + self_off));
    int e  = g_rowptr[node];
    int e1 = g_rowptr[node + 1];
    for (; e + 8 <= e1; e += 8) {
        uint32_t off[8];
        uint4 v[8];
        #pragma unroll
        for (int j = 0; j < 8; j++) off[j] = (uint32_t)g_col[e + j] >> SH;
        #pragma unroll
        for (int j = 0; j < 8; j++) v[j] = *reinterpret_cast<const uint4*>(base + off[j]);
        uint4 w0 = hadd2x4(v[0], v[1]);
        uint4 w1 = hadd2x4(v[2], v[3]);
        uint4 w2 = hadd2x4(v[4], v[5]);
        uint4 w3 = hadd2x4(v[6], v[7]);
        add8(acc, hadd2x4(hadd2x4(w0, w1), hadd2x4(w2, w3)));
    }
    for (; e + 2 <= e1; e += 2) {
        uint4 v0 = *reinterpret_cast<const uint4*>(base + ((uint32_t)g_col[e] >> SH));
        uint4 v1 = *reinterpret_cast<const uint4*>(base + ((uint32_t)g_col[e + 1] >> SH));
        add8(acc, hadd2x4(v0, v1));
    }
    if (e < e1)
        add8(acc, *reinterpret_cast<const uint4*>(base + ((uint32_t)g_col[e] >> SH)));
}

// standalone agg (round-14 template, verbatim semantics)
template <int F, int SH, bool BIAS, bool RELU, bool OUT32>
__global__ void agg16_kernel(const __half* __restrict__ g,
                             const float* __restrict__ bias,
                             __half* __restrict__ outh,
                             float* __restrict__ outf, int n) {
    constexpr int TPN = F / 8;
    constexpr uint32_t RB = F * 2;
    int npb  = blockDim.x / TPN;
    int node = blockIdx.x * npb + threadIdx.x / TPN;
    if (node >= n) return;
    int lane = threadIdx.x % TPN;

    const char* base = (const char*)g + lane * 16;
    float acc[8];
    #pragma unroll
    for (int q = 0; q < 8; q++) acc[q] = 0.0f;
    agg_node<SH>(base, (uint32_t)node * RB, node, acc);

    float di = g_dinv[node];
    #pragma unroll
    for (int q = 0; q < 8; q++) acc[q] *= di;
    if (BIAS) {
        const float4* bp = (const float4*)(bias + lane * 8);
        float4 b0 = bp[0], b1 = bp[1];
        acc[0] += b0.x; acc[1] += b0.y; acc[2] += b0.z; acc[3] += b0.w;
        acc[4] += b1.x; acc[5] += b1.y; acc[6] += b1.z; acc[7] += b1.w;
    }
    if (RELU) {
        #pragma unroll
        for (int q = 0; q < 8; q++) acc[q] = fmaxf(acc[q], 0.0f);
    }
    if constexpr (OUT32) {
        size_t o = (size_t)node * F + lane * 8;
        *reinterpret_cast<float4*>(outf + o)     = make_float4(acc[0], acc[1], acc[2], acc[3]);
        *reinterpret_cast<float4*>(outf + o + 4) = make_float4(acc[4], acc[5], acc[6], acc[7]);
    } else {
        uint4 o16;
        __half2 p0 = __floats2half2_rn(acc[0], acc[1]);
        __half2 p1 = __floats2half2_rn(acc[2], acc[3]);
        __half2 p2 = __floats2half2_rn(acc[4], acc[5]);
        __half2 p3 = __floats2half2_rn(acc[6], acc[7]);
        o16.x = *reinterpret_cast<uint32_t*>(&p0);
        o16.y = *reinterpret_cast<uint32_t*>(&p1);
        o16.z = *reinterpret_cast<uint32_t*>(&p2);
        o16.w = *reinterpret_cast<uint32_t*>(&p3);
        *reinterpret_cast<uint4*>(outh + (size_t)node * F + lane * 8) = o16;
    }
}

// ---------------- launch 5: FUSED GEMM1+GEMM2 (round-14 verbatim) ------------
#define LDS1 40
#define LDS2 264
#define G12_SMEM ((2 * (128 + 256) * LDS1 + 2 * 128 * LDS2) * 2)   // 196608 B

__global__ __launch_bounds__(256)
void gemm12_kernel(const __half* __restrict__ A, const __half* __restrict__ W1t,
                   const __half* __restrict__ W2t, const float* __restrict__ b1,
                   __half* __restrict__ g2) {
    constexpr int KC = 32;
    constexpr int SSZ = (128 + 256) * LDS1;
    extern __shared__ __half sm[];
    __half* h1t = sm + 2 * SSZ;
    uint32_t u_stg = smem_u32(sm);
    uint32_t u_h1  = smem_u32(h1t);
    uint32_t u_w2  = u_h1 + 128 * LDS2 * 2;

    int tid = threadIdx.x, wid = tid >> 5, lane = tid & 31;
    int wm0 = (wid >> 2) * 64;
    int wn0 = (wid & 3) * 64;
    int m0  = blockIdx.x * 128;

    int a_r = lane & 15, a_c = (lane >> 4) * 8;
    int b_r = lane & 7,  b_c = ((lane >> 3) & 1) * 8;

    for (int i = tid; i < 128 * 32; i += 256) {
        int r = i >> 5, c = i & 31;
        cp16(u_w2 + (uint32_t)(r * LDS2 + c * 8) * 2, W2t + (size_t)r * 256 + c * 8);
    }

    auto issue = [&](int ch, int st) {
        int kc = ch * KC;
        uint32_t ub = u_stg + (uint32_t)st * SSZ * 2;
        for (int i = tid; i < 128 * 4; i += 256) {
            int r = i >> 2, c = i & 3;
            cp16(ub + (uint32_t)(r * LDS1 + c * 8) * 2,
                 A + (size_t)(m0 + r) * 128 + kc + c * 8);
        }
        for (int i = tid; i < 256 * 4; i += 256) {
            int r = i >> 2, c = i & 3;
            cp16(ub + (uint32_t)((128 + r) * LDS1 + c * 8) * 2,
                 W1t + (size_t)r * 128 + kc + c * 8);
        }
        CP_COMMIT();
    };

    float acc[4][8][4];
    #pragma unroll
    for (int i = 0; i < 4; i++)
        #pragma unroll
        for (int j = 0; j < 8; j++)
            #pragma unroll
            for (int q = 0; q < 4; q++) acc[i][j][q] = 0.0f;

    issue(0, 0);
    #pragma unroll
    for (int ch = 0; ch < 4; ch++) {
        if (ch + 1 < 4) {
            issue(ch + 1, (ch + 1) & 1);
            asm volatile("cp.async.wait_group 1;" ::: "memory");
        } else {
            asm volatile("cp.async.wait_group 0;" ::: "memory");
        }
        __syncthreads();
        uint32_t ub = u_stg + (uint32_t)(ch & 1) * SSZ * 2;
        #pragma unroll
        for (int ks = 0; ks < 2; ks++) {
            int k0 = ks * 16;
            uint32_t a[4][4], b[8][2];
            #pragma unroll
            for (int i = 0; i < 4; i++)
                ldsm4(ub + (uint32_t)((wm0 + i * 16 + a_r) * LDS1 + k0 + a_c) * 2, a[i]);
            #pragma unroll
            for (int j = 0; j < 8; j++)
                ldsm2(ub + (uint32_t)((128 + wn0 + j * 8 + b_r) * LDS1 + k0 + b_c) * 2, b[j]);
            #pragma unroll
            for (int i = 0; i < 4; i++)
                #pragma unroll
                for (int j = 0; j < 8; j++)
                    mma16816h(acc[i][j], a[i], b[j]);
        }
        __syncthreads();
    }

    int gr = lane >> 2, t = lane & 3;
    #pragma unroll
    for (int i = 0; i < 4; i++) {
        #pragma unroll
        for (int j = 0; j < 8; j++) {
            int col = wn0 + j * 8 + 2 * t;
            #pragma unroll
            for (int h = 0; h < 2; h++) {
                int rl = wm0 + i * 16 + gr + h * 8;
                float v0 = acc[i][j][h * 2 + 0] + b1[col];
                float v1 = acc[i][j][h * 2 + 1] + b1[col + 1];
                v0 = fmaxf(v0, 0.f); v1 = fmaxf(v1, 0.f);
                *reinterpret_cast<__half2*>(&h1t[rl * LDS2 + col]) =
                    __floats2half2_rn(v0, v1);
            }
        }
    }
    __syncthreads();

    float acc2[4][4][4];
    #pragma unroll
    for (int i = 0; i < 4; i++)
        #pragma unroll
        for (int j = 0; j < 4; j++)
            #pragma unroll
            for (int q = 0; q < 4; q++) acc2[i][j][q] = 0.0f;
    int wn2 = (wid & 3) * 32;
    #pragma unroll
    for (int ks = 0; ks < 16; ks++) {
        int k0 = ks * 16;
        uint32_t a[4][4], b[4][2];
        #pragma unroll
        for (int i = 0; i < 4; i++)
            ldsm4(u_h1 + (uint32_t)((wm0 + i * 16 + a_r) * LDS2 + k0 + a_c) * 2, a[i]);
        #pragma unroll
        for (int j = 0; j < 4; j++)
            ldsm2(u_w2 + (uint32_t)((wn2 + j * 8 + b_r) * LDS2 + k0 + b_c) * 2, b[j]);
        #pragma unroll
        for (int i = 0; i < 4; i++)
            #pragma unroll
            for (int j = 0; j < 4; j++)
                mma16816h(acc2[i][j], a[i], b[j]);
    }

    #pragma unroll
    for (int i = 0; i < 4; i++) {
        #pragma unroll
        for (int j = 0; j < 4; j++) {
            int col = wn2 + j * 8 + 2 * t;
            #pragma unroll
            for (int h = 0; h < 2; h++) {
                int row = m0 + wm0 + i * 16 + gr + h * 8;
                float d = g_dinv[row];
                float v0 = acc2[i][j][h * 2 + 0] * d;
                float v1 = acc2[i][j][h * 2 + 1] * d;
                *reinterpret_cast<__half2*>(g2 + (size_t)row * F_H + col) =
                    __floats2half2_rn(v0, v1);
            }
        }
    }
}

// ---------------- launch 6: FUSED agg2 + GEMM3 (no shfl) ---------------------
#define LDSB 136
#define AG3_SMEM ((128 * LDSB + 32 * LDSB) * 2)   // 43520 B

__global__ __launch_bounds__(256)
void agg_gemm3_kernel(const __half* __restrict__ g2, const float* __restrict__ b2,
                      const __half* __restrict__ W3t, __half* __restrict__ g3, int n) {
    extern __shared__ __half smB[];
    uint32_t u_h2 = smem_u32(smB);
    uint32_t u_w3 = u_h2 + 128 * LDSB * 2;

    int tid = threadIdx.x, wid = tid >> 5, lane = tid & 31;
    int m0 = blockIdx.x * 128;

    // preload W3 [32][128] (hidden behind the agg phase)
    for (int i = tid; i < 32 * 16; i += 256) {
        int r = i >> 4, c = i & 15;
        cp16(u_w3 + (uint32_t)(r * LDSB + c * 8) * 2, W3t + (size_t)r * 128 + c * 8);
    }
    CP_COMMIT();

    // ---- agg phase: 16 node-groups of 16 lanes; 8 passes for 128 rows ----
    int lg = tid & 15;
    int grp = tid >> 4;
    const char* base = (const char*)g2 + lg * 16;
    const float4* bp = (const float4*)(b2 + lg * 8);
    float4 bb0 = bp[0], bb1 = bp[1];

    #pragma unroll 1
    for (int it = 0; it < 8; it++) {
        int rl = it * 16 + grp;
        int node = m0 + rl;
        float acc[8];
        #pragma unroll
        for (int q = 0; q < 8; q++) acc[q] = 0.0f;
        if (node < n) {
            agg_node<0>(base, (uint32_t)node * 256, node, acc);
            float di = g_dinv[node];
            acc[0] = fmaxf(acc[0] * di + bb0.x, 0.f);
            acc[1] = fmaxf(acc[1] * di + bb0.y, 0.f);
            acc[2] = fmaxf(acc[2] * di + bb0.z, 0.f);
            acc[3] = fmaxf(acc[3] * di + bb0.w, 0.f);
            acc[4] = fmaxf(acc[4] * di + bb1.x, 0.f);
            acc[5] = fmaxf(acc[5] * di + bb1.y, 0.f);
            acc[6] = fmaxf(acc[6] * di + bb1.z, 0.f);
            acc[7] = fmaxf(acc[7] * di + bb1.w, 0.f);
        }
        uint4 o16;
        __half2 p0 = __floats2half2_rn(acc[0], acc[1]);
        __half2 p1 = __floats2half2_rn(acc[2], acc[3]);
        __half2 p2 = __floats2half2_rn(acc[4], acc[5]);
        __half2 p3 = __floats2half2_rn(acc[6], acc[7]);
        o16.x = *reinterpret_cast<uint32_t*>(&p0);
        o16.y = *reinterpret_cast<uint32_t*>(&p1);
        o16.z = *reinterpret_cast<uint32_t*>(&p2);
        o16.w = *reinterpret_cast<uint32_t*>(&p3);
        *reinterpret_cast<uint4*>(smB + rl * LDSB + lg * 8) = o16;
    }
    asm volatile("cp.async.wait_group 0;" ::: "memory");
    __syncthreads();

    // ---- GEMM3: [128,32] = h2t[128,128] @ W3^T; 8 warps, WM=16, NF=4 ----
    int wm0 = wid * 16;
    int a_r = lane & 15, a_c = (lane >> 4) * 8;
    int b_r = lane & 7,  b_c = ((lane >> 3) & 1) * 8;
    float acc2[4][4];
    #pragma unroll
    for (int j = 0; j < 4; j++)
        #pragma unroll
        for (int q = 0; q < 4; q++) acc2[j][q] = 0.0f;

    #pragma unroll
    for (int ks = 0; ks < 8; ks++) {
        int k0 = ks * 16;
        uint32_t a[4], b[4][2];
        ldsm4(u_h2 + (uint32_t)((wm0 + a_r) * LDSB + k0 + a_c) * 2, a);
        #pragma unroll
        for (int j = 0; j < 4; j++)
            ldsm2(u_w3 + (uint32_t)((j * 8 + b_r) * LDSB + k0 + b_c) * 2, b[j]);
        #pragma unroll
        for (int j = 0; j < 4; j++)
            mma16816h(acc2[j], a, b[j]);
    }

    int gr = lane >> 2, t = lane & 3;
    #pragma unroll
    for (int j = 0; j < 4; j++) {
        int col = j * 8 + 2 * t;
        #pragma unroll
        for (int h = 0; h < 2; h++) {
            int row = m0 + wm0 + gr + h * 8;
            float d = g_dinv[row];
            float v0 = acc2[j][h * 2 + 0] * d;
            float v1 = acc2[j][h * 2 + 1] * d;
            *reinterpret_cast<__half2*>(g3 + (size_t)row * F_OUT + col) =
                __floats2half2_rn(v0, v1);
        }
    }
}

// ---------------- driver -----------------------------------------------------
extern "C" void kernel_launch(void* const* d_in, const int* in_sizes, int n_in,
                              void* d_out, int out_size) {
    const float* x  = (const float*)d_in[0];
    const int*   ei = (const int*)d_in[1];       // int32 (JAX x64 disabled)
    const float* W1 = (const float*)d_in[2];
    const float* b1 = (const float*)d_in[3];
    const float* W2 = (const float*)d_in[4];
    const float* b2 = (const float*)d_in[5];
    const float* W3 = (const float*)d_in[6];
    const float* b3 = (const float*)d_in[7];
    float*       out = (float*)d_out;

    const int n = in_sizes[0] / F_IN;   // 50000
    const int e = in_sizes[1] / 2;      // 800000

    __half *x16, *a1, *g2, *g3, *w1, *w2, *w3;
    cudaGetSymbolAddress((void**)&x16, g_x16);
    cudaGetSymbolAddress((void**)&a1,  g_a1);
    cudaGetSymbolAddress((void**)&g2,  g_g2);
    cudaGetSymbolAddress((void**)&g3,  g_g3);
    cudaGetSymbolAddress((void**)&w1,  g_w1);
    cudaGetSymbolAddress((void**)&w2,  g_w2);
    cudaGetSymbolAddress((void**)&w3,  g_w3);

    cudaFuncSetAttribute(gemm12_kernel,
                         cudaFuncAttributeMaxDynamicSharedMemorySize, G12_SMEM);
    cudaFuncSetAttribute(agg_gemm3_kernel,
                         cudaFuncAttributeMaxDynamicSharedMemorySize, AG3_SMEM);

    const int mt = M_PAD / 128;           // 391 row tiles
    const int nb = (n + 1023) / 1024;     // 49 scan blocks

    // launch 1: degree(x4/thread) + weight transpose + scan-flag reset
    const int B_deg = (e / 4 + 255) / 256;
    const int B_w   = (65536 + 4096 + 255) / 256;
    prep_kernel<<<B_deg + B_w + 1, 256>>>(ei, W1, W2, W3, w1, w2, w3,
                                          e, B_deg, B_w);

    // launch 2: chained scan (dinv, rowptr, cursor, count reset)
    scan_chained_kernel<<<nb, 1024>>>(n, nb);

    // launch 3: FUSED csr-fill (src<<8) + x->prescaled-fp16
    const int B_fill = (e + 255) / 256;
    const int B_conv = (n * 16 + 255) / 256;
    convfill_kernel<<<B_fill + B_conv, 256>>>(x, x16, ei, n, e, B_fill);

    // launch 4: agg1 (pure sum) -> a1
    agg16_kernel<F_IN, 0, false, false, false><<<(n + 7) / 8, 128>>>(
        x16, nullptr, a1, nullptr, n);

    // launch 5: FUSED GEMM1+GEMM2 -> g2 (dinv-prescaled)
    gemm12_kernel<<<mt, 256, G12_SMEM>>>(a1, w1, w2, b1, g2);

    // launch 6: FUSED agg2 + GEMM3 -> g3 (dinv-prescaled)
    agg_gemm3_kernel<<<mt, 256, AG3_SMEM>>>(g2, b2, w3, g3, n);

    // launch 7: agg3 + b3 -> out fp32 (g3 rows 64B: offsets >>2)
    agg16_kernel<F_OUT, 2, true, false, true><<<(n + 31) / 32, 128>>>(
        g3, b3, nullptr, out, n);
}

// round 17
// speedup vs baseline: 1.0147x; 1.0147x over previous
#include <cuda_runtime.h>
#include <cuda_fp16.h>
#include <cstdint>

// Problem constants (fixed by dataset)
#define N_NODES 50000
#define N_EDGES 800000
#define F_IN   128
#define F_H1   256
#define F_H    128
#define F_OUT  32
#define M_PAD  50048   // 391 * 128

// ---------------- scratch (static device globals) ---------------------------
__device__ int   g_count [N_NODES];
__device__ float g_dinv  [M_PAD];        // pad rows stay 0
__device__ int   g_rowptr[N_NODES + 1];
__device__ int   g_pos   [N_EDGES];      // per-edge slot within dst bucket
__device__ int   g_col   [N_EDGES];      // stores src<<8 (byte offset, 256B rows)
__device__ int   g_pfx   [64];           // chained-scan prefix (+1; 0 = not ready)

// fp16 activations
__device__ __half g_x16[(size_t)N_NODES * F_IN];   // dinv-prescaled fp16 x
__device__ __half g_a1 [(size_t)M_PAD * F_IN];     // agg1 out; pad rows stay 0
__device__ __half g_g2 [(size_t)M_PAD * F_H];      // dinv*(relu(a1@W1+b1)@W2)
__device__ __half g_h2 [(size_t)M_PAD * F_H];
__device__ __half g_g3 [(size_t)M_PAD * F_OUT];
// transposed fp16 weights [N][K] (K-major rows)
__device__ __half g_w1[256 * 128];
__device__ __half g_w2[128 * 256];
__device__ __half g_w3[32 * 128];

// ---------------- PTX helpers ------------------------------------------------
__device__ __forceinline__ uint32_t smem_u32(const void* p) {
    uint32_t a;
    asm("{ .reg .u64 t; cvta.to.shared.u64 t, %1; cvt.u32.u64 %0, t; }"
        : "=r"(a) : "l"(p));
    return a;
}
__device__ __forceinline__ void ldsm4(uint32_t addr, uint32_t r[4]) {
    asm volatile("ldmatrix.sync.aligned.m8n8.x4.shared.b16 {%0,%1,%2,%3}, [%4];"
                 : "=r"(r[0]), "=r"(r[1]), "=r"(r[2]), "=r"(r[3]) : "r"(addr));
}
__device__ __forceinline__ void ldsm2(uint32_t addr, uint32_t r[2]) {
    asm volatile("ldmatrix.sync.aligned.m8n8.x2.shared.b16 {%0,%1}, [%2];"
                 : "=r"(r[0]), "=r"(r[1]) : "r"(addr));
}
__device__ __forceinline__ void mma16816h(float* c, const uint32_t* a, const uint32_t* b) {
    asm volatile(
        "mma.sync.aligned.m16n8k16.row.col.f32.f16.f16.f32 "
        "{%0,%1,%2,%3}, {%4,%5,%6,%7}, {%8,%9}, {%0,%1,%2,%3};"
        : "+f"(c[0]), "+f"(c[1]), "+f"(c[2]), "+f"(c[3])
        : "r"(a[0]), "r"(a[1]), "r"(a[2]), "r"(a[3]), "r"(b[0]), "r"(b[1]));
}
__device__ __forceinline__ void cp16(uint32_t saddr, const void* gaddr) {
    asm volatile("cp.async.cg.shared.global [%0], [%1], 16;"
                 :: "r"(saddr), "l"(gaddr));
}
#define CP_COMMIT() asm volatile("cp.async.commit_group;" ::: "memory")

// ---------------- launch 1: fused prep (degree+pos(x4) + W transp + flags) ---
__global__ __launch_bounds__(256)
void prep_kernel(const int* __restrict__ ei,
                 const float* __restrict__ W1, const float* __restrict__ W2,
                 const float* __restrict__ W3,
                 __half* w1, __half* w2, __half* w3,
                 int e, int B_deg, int B_w) {
    int bid = blockIdx.x, tid = threadIdx.x;
    if (bid < B_deg) {               // degree atomics, 4/thread, capture slot
        int i0 = (bid * 256 + tid) * 4;
        if (i0 + 4 <= e) {
            int4 d = *reinterpret_cast<const int4*>(ei + e + i0);
            int4 p;
            p.x = atomicAdd(&g_count[d.x], 1);
            p.y = atomicAdd(&g_count[d.y], 1);
            p.z = atomicAdd(&g_count[d.z], 1);
            p.w = atomicAdd(&g_count[d.w], 1);
            *reinterpret_cast<int4*>(g_pos + i0) = p;
        } else {
            for (int j = i0; j < e; j++)
                g_pos[j] = atomicAdd(&g_count[ei[e + j]], 1);
        }
    } else if (bid < B_deg + B_w) {                      // weight transpose (fp16)
        int idx = (bid - B_deg) * 256 + tid;
        if (idx < 32768) {                               // W1 [128,256] -> [256][128]
            int nn = idx / 128, k = idx % 128;
            w1[idx] = __float2half(W1[k * 256 + nn]);
        } else if (idx < 65536) {                        // W2 [256,128] -> [128][256]
            int i2 = idx - 32768;
            int nn = i2 / 256, k = i2 % 256;
            w2[i2] = __float2half(W2[k * 128 + nn]);
        } else if (idx < 65536 + 4096) {                 // W3 [128,32] -> [32][128]
            int i3 = idx - 65536;
            int nn = i3 / 128, k = i3 % 128;
            w3[i3] = __float2half(W3[k * 32 + nn]);
        }
    } else {
        if (tid < 64) g_pfx[tid] = 0;
    }
}

// ---------------- launch 2: chained single-pass scan -------------------------
__global__ __launch_bounds__(1024)
void scan_chained_kernel(int n, int nb) {
    __shared__ int temp[1024];
    __shared__ int pfx_sh;
    int bid = blockIdx.x, tid = threadIdx.x;
    int i = bid * 1024 + tid;
    int v = (i < n) ? g_count[i] : 0;
    if (i < n) {
        g_dinv[i]  = rsqrtf((float)(v + 1));   // +1 self-loop
        g_count[i] = 0;                        // reset for next replay
    }
    temp[tid] = v;
    __syncthreads();
    #pragma unroll
    for (int off = 1; off < 1024; off <<= 1) {
        int t = (tid >= off) ? temp[tid - off] : 0;
        __syncthreads();
        temp[tid] += t;
        __syncthreads();
    }
    if (tid == 0) {
        int p = 0;
        if (bid > 0) {
            while ((p = atomicAdd(&g_pfx[bid - 1], 0)) == 0) __nanosleep(20);
            p -= 1;
        }
        atomicExch(&g_pfx[bid], p + temp[1023] + 1);
        pfx_sh = p;
    }
    __syncthreads();
    int base = pfx_sh;
    if (i < n) g_rowptr[i] = base + temp[tid] - v;
    if (bid == nb - 1 && tid == 1023) g_rowptr[n] = base + temp[1023];
}

// ---------------- launch 3: FUSED atomic-free csr-fill + x-convert -----------
__global__ __launch_bounds__(256)
void convfill_kernel(const float* __restrict__ x, __half* __restrict__ x16,
                     const int* __restrict__ ei, int n, int e, int B_fill) {
    int bid = blockIdx.x, tid = threadIdx.x;
    if (bid < B_fill) {                  // fill: NO atomics (pos from degree pass)
        int i = bid * 256 + tid;
        if (i < e) {
            int src = ei[i];
            int dst = ei[e + i];
            int pos = g_rowptr[dst] + g_pos[i];
            g_col[pos] = src << 8;       // pre-shifted byte offset
        }
    } else {                             // x -> dinv-prescaled fp16
        int i = (bid - B_fill) * 256 + tid;
        int node = i >> 4, lane = i & 15;
        if (node >= n) return;
        float di = g_dinv[node];
        const float4* xv = (const float4*)x;
        float4 a = xv[(size_t)node * 32 + lane * 2];
        float4 b = xv[(size_t)node * 32 + lane * 2 + 1];
        __half2 h0 = __floats2half2_rn(di * a.x, di * a.y);
        __half2 h1 = __floats2half2_rn(di * a.z, di * a.w);
        __half2 h2 = __floats2half2_rn(di * b.x, di * b.y);
        __half2 h3 = __floats2half2_rn(di * b.z, di * b.w);
        uint4 o;
        o.x = *reinterpret_cast<uint32_t*>(&h0);
        o.y = *reinterpret_cast<uint32_t*>(&h1);
        o.z = *reinterpret_cast<uint32_t*>(&h2);
        o.w = *reinterpret_cast<uint32_t*>(&h3);
        *reinterpret_cast<uint4*>(x16 + (size_t)node * F_IN + lane * 8) = o;
    }
}

// ---------------- fp16 pull aggregation (pre-shifted offsets, depth-3 tree) --
__device__ __forceinline__ void add8(float* acc, uint4 v) {
    const __half2* h = reinterpret_cast<const __half2*>(&v);
    #pragma unroll
    for (int q = 0; q < 4; q++) {
        float2 f = __half22float2(h[q]);
        acc[2 * q] += f.x; acc[2 * q + 1] += f.y;
    }
}
__device__ __forceinline__ uint4 hadd2x4(uint4 a, uint4 b) {
    const __half2* pa = reinterpret_cast<const __half2*>(&a);
    const __half2* pb = reinterpret_cast<const __half2*>(&b);
    uint4 r;
    __half2* pr = reinterpret_cast<__half2*>(&r);
    #pragma unroll
    for (int q = 0; q < 4; q++) pr[q] = __hadd2(pa[q], pb[q]);
    return r;
}

// out[d] = dinv[d]*(g[d] + sum g[s]) (+bias)(relu); g rows dinv[src]-prescaled.
// g_col holds src<<8 (byte offset for 256B rows); SH shifts down for smaller F.
template <int F, int SH, bool BIAS, bool RELU, bool OUT32>
__global__ void agg16_kernel(const __half* __restrict__ g,
                             const float* __restrict__ bias,
                             __half* __restrict__ outh,
                             float* __restrict__ outf, int n) {
    constexpr int TPN = F / 8;
    constexpr uint32_t RB = F * 2;
    int npb  = blockDim.x / TPN;
    int node = blockIdx.x * npb + threadIdx.x / TPN;
    if (node >= n) return;
    int lane = threadIdx.x % TPN;

    const char* base = (const char*)g + lane * 16;
    float acc[8];
    #pragma unroll
    for (int q = 0; q < 8; q++) acc[q] = 0.0f;
    add8(acc, *reinterpret_cast<const uint4*>(base + (uint32_t)node * RB));  // self

    int e  = g_rowptr[node];
    int e1 = g_rowptr[node + 1];
    for (; e + 8 <= e1; e += 8) {
        uint32_t off[8];
        uint4 v[8];
        #pragma unroll
        for (int j = 0; j < 8; j++) off[j] = (uint32_t)g_col[e + j] >> SH;
        #pragma unroll
        for (int j = 0; j < 8; j++) v[j] = *reinterpret_cast<const uint4*>(base + off[j]);
        uint4 w0 = hadd2x4(v[0], v[1]);
        uint4 w1 = hadd2x4(v[2], v[3]);
        uint4 w2 = hadd2x4(v[4], v[5]);
        uint4 w3 = hadd2x4(v[6], v[7]);
        uint4 u0 = hadd2x4(w0, w1);
        uint4 u1 = hadd2x4(w2, w3);
        add8(acc, hadd2x4(u0, u1));
    }
    for (; e + 2 <= e1; e += 2) {
        uint4 v0 = *reinterpret_cast<const uint4*>(base + ((uint32_t)g_col[e] >> SH));
        uint4 v1 = *reinterpret_cast<const uint4*>(base + ((uint32_t)g_col[e + 1] >> SH));
        add8(acc, hadd2x4(v0, v1));
    }
    if (e < e1)
        add8(acc, *reinterpret_cast<const uint4*>(base + ((uint32_t)g_col[e] >> SH)));

    float di = g_dinv[node];
    #pragma unroll
    for (int q = 0; q < 8; q++) acc[q] *= di;
    if (BIAS) {
        const float4* bp = (const float4*)(bias + lane * 8);
        float4 b0 = bp[0], b1 = bp[1];
        acc[0] += b0.x; acc[1] += b0.y; acc[2] += b0.z; acc[3] += b0.w;
        acc[4] += b1.x; acc[5] += b1.y; acc[6] += b1.z; acc[7] += b1.w;
    }
    if (RELU) {
        #pragma unroll
        for (int q = 0; q < 8; q++) acc[q] = fmaxf(acc[q], 0.0f);
    }
    if constexpr (OUT32) {
        size_t o = (size_t)node * F + lane * 8;
        *reinterpret_cast<float4*>(outf + o)     = make_float4(acc[0], acc[1], acc[2], acc[3]);
        *reinterpret_cast<float4*>(outf + o + 4) = make_float4(acc[4], acc[5], acc[6], acc[7]);
    } else {
        uint4 o16;
        __half2 p0 = __floats2half2_rn(acc[0], acc[1]);
        __half2 p1 = __floats2half2_rn(acc[2], acc[3]);
        __half2 p2 = __floats2half2_rn(acc[4], acc[5]);
        __half2 p3 = __floats2half2_rn(acc[6], acc[7]);
        o16.x = *reinterpret_cast<uint32_t*>(&p0);
        o16.y = *reinterpret_cast<uint32_t*>(&p1);
        o16.z = *reinterpret_cast<uint32_t*>(&p2);
        o16.w = *reinterpret_cast<uint32_t*>(&p3);
        *reinterpret_cast<uint4*>(outh + (size_t)node * F + lane * 8) = o16;
    }
}

// ---------------- FUSED GEMM1+GEMM2 ------------------------------------------
#define LDS1 40     // KC(32)+8
#define LDS2 264    // 256+8
#define G12_SMEM ((2 * (128 + 256) * LDS1 + 2 * 128 * LDS2) * 2)   // 196608 B

__global__ __launch_bounds__(256)
void gemm12_kernel(const __half* __restrict__ A, const __half* __restrict__ W1t,
                   const __half* __restrict__ W2t, const float* __restrict__ b1,
                   __half* __restrict__ g2) {
    constexpr int KC = 32;
    constexpr int SSZ = (128 + 256) * LDS1;
    extern __shared__ __half sm[];
    __half* h1t = sm + 2 * SSZ;
    uint32_t u_stg = smem_u32(sm);
    uint32_t u_h1  = smem_u32(h1t);
    uint32_t u_w2  = u_h1 + 128 * LDS2 * 2;

    int tid = threadIdx.x, wid = tid >> 5, lane = tid & 31;
    int wm0 = (wid >> 2) * 64;
    int wn0 = (wid & 3) * 64;
    int m0  = blockIdx.x * 128;

    int a_r = lane & 15, a_c = (lane >> 4) * 8;
    int b_r = lane & 7,  b_c = ((lane >> 3) & 1) * 8;

    for (int i = tid; i < 128 * 32; i += 256) {
        int r = i >> 5, c = i & 31;
        cp16(u_w2 + (uint32_t)(r * LDS2 + c * 8) * 2, W2t + (size_t)r * 256 + c * 8);
    }

    auto issue = [&](int ch, int st) {
        int kc = ch * KC;
        uint32_t ub = u_stg + (uint32_t)st * SSZ * 2;
        for (int i = tid; i < 128 * 4; i += 256) {
            int r = i >> 2, c = i & 3;
            cp16(ub + (uint32_t)(r * LDS1 + c * 8) * 2,
                 A + (size_t)(m0 + r) * 128 + kc + c * 8);
        }
        for (int i = tid; i < 256 * 4; i += 256) {
            int r = i >> 2, c = i & 3;
            cp16(ub + (uint32_t)((128 + r) * LDS1 + c * 8) * 2,
                 W1t + (size_t)r * 128 + kc + c * 8);
        }
        CP_COMMIT();
    };

    float acc[4][8][4];
    #pragma unroll
    for (int i = 0; i < 4; i++)
        #pragma unroll
        for (int j = 0; j < 8; j++)
            #pragma unroll
            for (int q = 0; q < 4; q++) acc[i][j][q] = 0.0f;

    issue(0, 0);
    #pragma unroll
    for (int ch = 0; ch < 4; ch++) {
        if (ch + 1 < 4) {
            issue(ch + 1, (ch + 1) & 1);
            asm volatile("cp.async.wait_group 1;" ::: "memory");
        } else {
            asm volatile("cp.async.wait_group 0;" ::: "memory");
        }
        __syncthreads();
        uint32_t ub = u_stg + (uint32_t)(ch & 1) * SSZ * 2;
        #pragma unroll
        for (int ks = 0; ks < 2; ks++) {
            int k0 = ks * 16;
            uint32_t a[4][4], b[8][2];
            #pragma unroll
            for (int i = 0; i < 4; i++)
                ldsm4(ub + (uint32_t)((wm0 + i * 16 + a_r) * LDS1 + k0 + a_c) * 2, a[i]);
            #pragma unroll
            for (int j = 0; j < 8; j++)
                ldsm2(ub + (uint32_t)((128 + wn0 + j * 8 + b_r) * LDS1 + k0 + b_c) * 2, b[j]);
            #pragma unroll
            for (int i = 0; i < 4; i++)
                #pragma unroll
                for (int j = 0; j < 8; j++)
                    mma16816h(acc[i][j], a[i], b[j]);
        }
        __syncthreads();
    }

    int gr = lane >> 2, t = lane & 3;
    #pragma unroll
    for (int i = 0; i < 4; i++) {
        #pragma unroll
        for (int j = 0; j < 8; j++) {
            int col = wn0 + j * 8 + 2 * t;
            #pragma unroll
            for (int h = 0; h < 2; h++) {
                int rl = wm0 + i * 16 + gr + h * 8;
                float v0 = acc[i][j][h * 2 + 0] + b1[col];
                float v1 = acc[i][j][h * 2 + 1] + b1[col + 1];
                v0 = fmaxf(v0, 0.f); v1 = fmaxf(v1, 0.f);
                *reinterpret_cast<__half2*>(&h1t[rl * LDS2 + col]) =
                    __floats2half2_rn(v0, v1);
            }
        }
    }
    __syncthreads();

    float acc2[4][4][4];
    #pragma unroll
    for (int i = 0; i < 4; i++)
        #pragma unroll
        for (int j = 0; j < 4; j++)
            #pragma unroll
            for (int q = 0; q < 4; q++) acc2[i][j][q] = 0.0f;
    int wn2 = (wid & 3) * 32;
    #pragma unroll
    for (int ks = 0; ks < 16; ks++) {
        int k0 = ks * 16;
        uint32_t a[4][4], b[4][2];
        #pragma unroll
        for (int i = 0; i < 4; i++)
            ldsm4(u_h1 + (uint32_t)((wm0 + i * 16 + a_r) * LDS2 + k0 + a_c) * 2, a[i]);
        #pragma unroll
        for (int j = 0; j < 4; j++)
            ldsm2(u_w2 + (uint32_t)((wn2 + j * 8 + b_r) * LDS2 + k0 + b_c) * 2, b[j]);
        #pragma unroll
        for (int i = 0; i < 4; i++)
            #pragma unroll
            for (int j = 0; j < 4; j++)
                mma16816h(acc2[i][j], a[i], b[j]);
    }

    #pragma unroll
    for (int i = 0; i < 4; i++) {
        #pragma unroll
        for (int j = 0; j < 4; j++) {
            int col = wn2 + j * 8 + 2 * t;
            #pragma unroll
            for (int h = 0; h < 2; h++) {
                int row = m0 + wm0 + i * 16 + gr + h * 8;
                float d = g_dinv[row];
                float v0 = acc2[i][j][h * 2 + 0] * d;
                float v1 = acc2[i][j][h * 2 + 1] * d;
                *reinterpret_cast<__half2*>(g2 + (size_t)row * F_H + col) =
                    __floats2half2_rn(v0, v1);
            }
        }
    }
}

// ---------------- generic fp16 GEMM (layer 3), cp.async 2-stage --------------
template <int NB, int K, int WARPS_M, int WARPS_N, bool BIAS, bool RELU, bool DINV>
__global__ __launch_bounds__(32 * WARPS_M * WARPS_N)
void gemm_f16(const __half* __restrict__ A, const __half* __restrict__ W,
              const float* __restrict__ bias,
              __half* __restrict__ C, int M, int Ntotal) {
    constexpr int BM  = 128;
    constexpr int KC  = 32;
    constexpr int LDS = KC + 8;
    constexpr int NT  = 32 * WARPS_M * WARPS_N;
    constexpr int WM  = BM / WARPS_M;
    constexpr int WN  = NB / WARPS_N;
    constexpr int MF  = WM / 16;
    constexpr int NF  = WN / 8;
    constexpr int NCH = K / KC;
    constexpr int C8  = KC / 8;
    constexpr int AOFF = 0;
    constexpr int WOFF = BM * LDS;
    constexpr int SSZ  = (BM + NB) * LDS;

    extern __shared__ __half sm[];
    uint32_t u0 = smem_u32(sm);

    int tid  = threadIdx.x;
    int wid  = tid >> 5, lane = tid & 31;
    int wm0  = (wid / WARPS_N) * WM;
    int wn0  = (wid % WARPS_N) * WN;
    int m0   = blockIdx.x * BM;
    int n0   = blockIdx.y * NB;

    int a_r = lane & 15, a_c = (lane >> 4) * 8;
    int b_r = lane & 7,  b_c = ((lane >> 3) & 1) * 8;

    float acc[MF][NF][4];
    #pragma unroll
    for (int i = 0; i < MF; i++)
        #pragma unroll
        for (int j = 0; j < NF; j++)
            #pragma unroll
            for (int q = 0; q < 4; q++) acc[i][j][q] = 0.0f;

    auto issue = [&](int ch, int st) {
        int kc = ch * KC;
        uint32_t ub = u0 + (uint32_t)st * SSZ * 2;
        for (int i = tid; i < BM * C8; i += NT) {
            int r = i / C8, c = i % C8;
            cp16(ub + AOFF * 2 + (uint32_t)(r * LDS + c * 8) * 2,
                 A + (size_t)(m0 + r) * K + kc + c * 8);
        }
        for (int i = tid; i < NB * C8; i += NT) {
            int r = i / C8, c = i % C8;
            cp16(ub + WOFF * 2 + (uint32_t)(r * LDS + c * 8) * 2,
                 W + (size_t)(n0 + r) * K + kc + c * 8);
        }
        CP_COMMIT();
    };

    issue(0, 0);
    #pragma unroll
    for (int ch = 0; ch < NCH; ch++) {
        if (ch + 1 < NCH) {
            issue(ch + 1, (ch + 1) & 1);
            asm volatile("cp.async.wait_group 1;" ::: "memory");
        } else {
            asm volatile("cp.async.wait_group 0;" ::: "memory");
        }
        __syncthreads();

        uint32_t ub = u0 + (uint32_t)(ch & 1) * SSZ * 2;
        #pragma unroll
        for (int ks = 0; ks < KC / 16; ks++) {
            int k0 = ks * 16;
            uint32_t a[MF][4], b[NF][2];
            #pragma unroll
            for (int i = 0; i < MF; i++) {
                uint32_t off = (uint32_t)((wm0 + i * 16 + a_r) * LDS + k0 + a_c) * 2;
                ldsm4(ub + AOFF * 2 + off, a[i]);
            }
            #pragma unroll
            for (int j = 0; j < NF; j++) {
                uint32_t off = (uint32_t)((wn0 + j * 8 + b_r) * LDS + k0 + b_c) * 2;
                ldsm2(ub + WOFF * 2 + off, b[j]);
            }
            #pragma unroll
            for (int i = 0; i < MF; i++)
                #pragma unroll
                for (int j = 0; j < NF; j++)
                    mma16816h(acc[i][j], a[i], b[j]);
        }
        __syncthreads();
    }

    int gr = lane >> 2, t = lane & 3;
    #pragma unroll
    for (int i = 0; i < MF; i++) {
        #pragma unroll
        for (int j = 0; j < NF; j++) {
            int col = n0 + wn0 + j * 8 + 2 * t;
            #pragma unroll
            for (int h = 0; h < 2; h++) {
                int row = m0 + wm0 + i * 16 + gr + h * 8;
                float v0 = acc[i][j][h * 2 + 0];
                float v1 = acc[i][j][h * 2 + 1];
                if (BIAS) { v0 += bias[col]; v1 += bias[col + 1]; }
                if (RELU) { v0 = fmaxf(v0, 0.f); v1 = fmaxf(v1, 0.f); }
                if (DINV) { float d = g_dinv[row]; v0 *= d; v1 *= d; }
                *reinterpret_cast<__half2*>(C + (size_t)row * Ntotal + col) =
                    __floats2half2_rn(v0, v1);
            }
        }
    }
}

// ---------------- driver -----------------------------------------------------
extern "C" void kernel_launch(void* const* d_in, const int* in_sizes, int n_in,
                              void* d_out, int out_size) {
    const float* x  = (const float*)d_in[0];
    const int*   ei = (const int*)d_in[1];       // int32 (JAX x64 disabled)
    const float* W1 = (const float*)d_in[2];
    const float* b1 = (const float*)d_in[3];
    const float* W2 = (const float*)d_in[4];
    const float* b2 = (const float*)d_in[5];
    const float* W3 = (const float*)d_in[6];
    const float* b3 = (const float*)d_in[7];
    float*       out = (float*)d_out;

    const int n = in_sizes[0] / F_IN;   // 50000
    const int e = in_sizes[1] / 2;      // 800000

    __half *x16, *a1, *g2, *h2, *g3, *w1, *w2, *w3;
    cudaGetSymbolAddress((void**)&x16, g_x16);
    cudaGetSymbolAddress((void**)&a1,  g_a1);
    cudaGetSymbolAddress((void**)&g2,  g_g2);
    cudaGetSymbolAddress((void**)&h2,  g_h2);
    cudaGetSymbolAddress((void**)&g3,  g_g3);
    cudaGetSymbolAddress((void**)&w1,  g_w1);
    cudaGetSymbolAddress((void**)&w2,  g_w2);
    cudaGetSymbolAddress((void**)&w3,  g_w3);

    const int smem32 = 2 * (128 + 32) * 40 * 2;   // 25600
    cudaFuncSetAttribute(gemm12_kernel,
                         cudaFuncAttributeMaxDynamicSharedMemorySize, G12_SMEM);
    cudaFuncSetAttribute(gemm_f16<32, 128, 8, 1, false, false, true>,
                         cudaFuncAttributeMaxDynamicSharedMemorySize, smem32);

    const int mt = M_PAD / 128;           // 391 row tiles
    const int nb = (n + 1023) / 1024;     // 49 scan blocks

    // launch 1: degree+pos(x4/thread) + weight transpose + scan-flag reset
    const int B_deg = (e / 4 + 255) / 256;
    const int B_w   = (65536 + 4096 + 255) / 256;
    prep_kernel<<<B_deg + B_w + 1, 256>>>(ei, W1, W2, W3, w1, w2, w3,
                                          e, B_deg, B_w);

    // launch 2: chained scan (dinv, rowptr, count reset)
    scan_chained_kernel<<<nb, 1024>>>(n, nb);

    // launch 3: FUSED atomic-free csr-fill (src<<8) + x->prescaled-fp16
    const int B_fill = (e + 255) / 256;
    const int B_conv = (n * 16 + 255) / 256;
    convfill_kernel<<<B_fill + B_conv, 256>>>(x, x16, ei, n, e, B_fill);

    // launch 4: agg1 (pure sum) -> a1
    agg16_kernel<F_IN, 0, false, false, false><<<(n + 7) / 8, 128>>>(
        x16, nullptr, a1, nullptr, n);

    // launch 5: FUSED GEMM1+GEMM2 -> g2 (dinv-prescaled)
    gemm12_kernel<<<mt, 256, G12_SMEM>>>(a1, w1, w2, b1, g2);

    // launch 6: agg2 + b2 + relu -> h2
    agg16_kernel<F_H, 0, true, true, false><<<(n + 7) / 8, 128>>>(
        g2, b2, h2, nullptr, n);

    // launch 7: GEMM3 (128->32) * dinv -> g3
    {
        dim3 grid(mt, 1);
        gemm_f16<32, 128, 8, 1, false, false, true><<<grid, 256, smem32>>>(
            h2, w3, nullptr, g3, n, F_OUT);
    }

    // launch 8: agg3 + b3 -> out fp32 (g3 rows 64B: offsets >>2)
    agg16_kernel<F_OUT, 2, true, false, true><<<(n + 31) / 32, 128>>>(
        g3, b3, nullptr, out, n);
}